// round 1
// baseline (speedup 1.0000x reference)
#include <cuda_runtime.h>
#include <math.h>

#define BS   256
#define NJ   55
#define NV   10475
#define NN   (NV*3)      // 31425
#define KSH  60
#define KPO  486
#define KTOT 546

__constant__ int c_parents[NJ] = {-1,0,0,0,1,2,3,4,5,6,7,8,9,9,9,12,13,14,16,17,18,19,
                                  15,15,15,20,25,26,20,28,29,20,31,32,20,34,35,20,37,38,
                                  21,40,41,21,43,44,21,46,47,21,49,50,21,52,53};

// ---- scratch (__device__ globals; no allocation allowed) ----
__device__ float g_Ft[KTOT*BS];            // feature matrix, transposed: Ft[k][b]
__device__ float g_rot[BS*NJ*9];           // rotation matrices
__device__ float g_JSDp[8*NJ*184];         // partial JSD reductions
__device__ float g_JSD[NJ*180];            // JSD[j][c*60+l]
__device__ float g_Jvt[NJ*3];              // J_regressor @ v_template
__device__ float g_joints[BS*NJ*3];
__device__ float g_Arel[BS*NJ*12];         // relative transforms (top 3 rows)
__device__ float g_vposed[BS*NN];          // 32.2 MB

// ============================================================================
// K1: Rodrigues + feature matrix build (rot_mats, pose_feature, betas)
// ============================================================================
__global__ void k_pose(const float* __restrict__ pose, const float* __restrict__ shape,
                       const float* __restrict__ expr, const float* __restrict__ go) {
    int b = blockIdx.x, t = threadIdx.x;
    if (t < NJ) {
        int j = t;
        float rx, ry, rz;
        if (j == 0)            { rx = go[0]; ry = go[1]; rz = go[2]; }
        else if (j==23||j==24) { rx = 0.f; ry = 0.f; rz = 0.f; }
        else {
            int src = (j <= 21) ? j : (j == 22 ? 52 : j - 3);
            const float* p = pose + (b*53 + src)*3;
            rx = p[0]; ry = p[1]; rz = p[2];
        }
        // match reference exactly: angle = ||rvec + 1e-8||, axis = rvec/angle
        float ax = rx + 1e-8f, ay = ry + 1e-8f, az = rz + 1e-8f;
        float angle = sqrtf(ax*ax + ay*ay + az*az);
        float inv = 1.f/angle;
        float x = rx*inv, y = ry*inv, z = rz*inv;
        float s = sinf(angle), c = cosf(angle), u = 1.f - c;
        float R[9];
        R[0] = 1.f - u*(y*y+z*z); R[1] = -s*z + u*x*y;      R[2] =  s*y + u*x*z;
        R[3] =  s*z + u*x*y;      R[4] = 1.f - u*(x*x+z*z); R[5] = -s*x + u*y*z;
        R[6] = -s*y + u*x*z;      R[7] =  s*x + u*y*z;      R[8] = 1.f - u*(x*x+y*y);
        float* rm = g_rot + (b*NJ + j)*9;
#pragma unroll
        for (int k = 0; k < 9; k++) rm[k] = R[k];
        if (j >= 1) {
            int kb = KSH + (j-1)*9;
#pragma unroll
            for (int k = 0; k < 9; k++)
                g_Ft[(kb+k)*BS + b] = R[k] - ((k==0||k==4||k==8) ? 1.f : 0.f);
        }
    }
    for (int i = t; i < KSH; i += 64)
        g_Ft[i*BS + b] = (i < 10) ? shape[b*10 + i] : expr[b*50 + (i-10)];
}

// ============================================================================
// K2: JSD partial = J_regressor @ shapedirs (compacted 60 cols) + Jvt partial
// ============================================================================
#define VCHUNK 1310
__global__ void k_jsdp(const float* __restrict__ Jr, const float* __restrict__ SD,
                       const float* __restrict__ vt) {
    int j = blockIdx.x, ch = blockIdx.y, t = threadIdx.x;
    int v0 = ch*VCHUNK;
    int v1 = min(v0 + VCHUNK, NV);
    int cnt = v1 - v0;
    __shared__ float jr_s[VCHUNK];
    for (int i = t; i < cnt; i += 192) jr_s[i] = Jr[j*NV + v0 + i];
    __syncthreads();
    float acc = 0.f;
    if (t < 180) {
        int c = t/60, l = t%60;
        int lsel = (l < 10) ? l : l + 290;
        const float* base = SD + c*350 + lsel;
#pragma unroll 4
        for (int i = 0; i < cnt; i++)
            acc += jr_s[i] * base[(v0+i)*1050];
    } else if (t < 183) {
        int c = t - 180;
#pragma unroll 4
        for (int i = 0; i < cnt; i++)
            acc += jr_s[i] * vt[(v0+i)*3 + c];
    }
    if (t < 183) g_JSDp[(ch*NJ + j)*184 + t] = acc;
}

// K3: finalize JSD / Jvt (sum 8 chunks)
__global__ void k_jsdf() {
    int j = blockIdx.x, t = threadIdx.x;
    if (t >= 183) return;
    float s = 0.f;
#pragma unroll
    for (int ch = 0; ch < 8; ch++) s += g_JSDp[(ch*NJ + j)*184 + t];
    if (t < 180) g_JSD[j*180 + t] = s;
    else         g_Jvt[j*3 + (t-180)] = s;
}

// ============================================================================
// K4: joints[b,j,c] = Jvt[j,c] + sum_l betas[b,l] * JSD[j,c,l]
// ============================================================================
__global__ void k_joints() {
    int b = blockIdx.x, t = threadIdx.x;
    __shared__ float fb[KSH];
    for (int i = t; i < KSH; i += 192) fb[i] = g_Ft[i*BS + b];
    __syncthreads();
    if (t < 165) {
        int j = t/3, c = t%3;
        float acc = g_Jvt[j*3 + c];
        const float* jsd = g_JSD + j*180 + c*60;
#pragma unroll
        for (int l = 0; l < KSH; l++) acc += fb[l]*jsd[l];
        g_joints[b*165 + t] = acc;
    }
}

// ============================================================================
// K5: kinematic chain (one warp per batch) -> A_rel, posed joints output
// ============================================================================
__global__ void k_chain(float* __restrict__ out_joints) {
    int b = blockIdx.x, t = threadIdx.x;
    __shared__ float A[NJ][12];
    __shared__ float jt[NJ][3];
    for (int i = t; i < 165; i += 32) jt[i/3][i%3] = g_joints[b*165 + i];
    __syncwarp();
    if (t < 12) {
        int m = t/4, n = t%4;
        A[0][t] = (n < 3) ? g_rot[(b*NJ)*9 + m*3 + n] : jt[0][m];
    }
    __syncwarp();
    for (int j = 1; j < NJ; j++) {
        if (t < 12) {
            int m = t/4, n = t%4;
            int p = c_parents[j];
            const float* rm = g_rot + (b*NJ + j)*9;
            float acc = (n == 3) ? A[p][m*4+3] : 0.f;
#pragma unroll
            for (int k = 0; k < 3; k++) {
                float tv = (n < 3) ? rm[k*3+n] : (jt[j][k] - jt[p][k]);
                acc += A[p][m*4+k]*tv;
            }
            A[j][t] = acc;
        }
        __syncwarp();
    }
    for (int e = t; e < 660; e += 32) {
        int j = e/12, r = e%12, m = r/4, n = r%4;
        float val = A[j][r];
        if (n == 3) {
            out_joints[b*165 + j*3 + m] = val;   // posed joints (pre-correction)
            val -= A[j][m*4+0]*jt[j][0] + A[j][m*4+1]*jt[j][1] + A[j][m*4+2]*jt[j][2];
        }
        g_Arel[b*660 + e] = val;
    }
}

// ============================================================================
// K6: blend GEMM  v_posed[b,n] = vt[n] + sum_k F[b,k] * D[k,n]
//     phase A: k in [0,60)   D from shapedirs (compacted, transposed in smem)
//     phase B: k in [60,546) D from posedirs (contiguous)
//     block tile 64b x 128n, thread tile 4b x 8n
// ============================================================================
#define BM_ 64
#define BN_ 128
#define KA_ 30
#define KB_ 18
#define DPAD 132
__global__ __launch_bounds__(256) void k_blend(const float* __restrict__ SD,
                                               const float* __restrict__ PD,
                                               const float* __restrict__ vt) {
    __shared__ float Fs[KA_*BM_];
    __shared__ float Ds[KA_*DPAD];
    int tid = threadIdx.x;
    int tx = tid % 16, ty = tid / 16;
    int n0 = blockIdx.x * BN_;
    int b0 = blockIdx.y * BM_;
    float acc[4][8];
#pragma unroll
    for (int i = 0; i < 4; i++)
#pragma unroll
        for (int jj = 0; jj < 8; jj++) acc[i][jj] = 0.f;

    // ---- phase A: shapedirs, k=0..59 in two 30-chunks ----
    for (int cchunk = 0; cchunk < 2; cchunk++) {
        int k0 = cchunk*KA_;
        for (int e = tid; e < KA_*BM_; e += 256) {
            int kk = e / BM_, bb = e % BM_;
            Fs[kk*BM_ + bb] = g_Ft[(k0+kk)*BS + b0 + bb];
        }
        for (int e = tid; e < KA_*BN_; e += 256) {
            int kk = e % KA_, nn = e / KA_;
            int k = k0 + kk;
            int lsel = (k < 10) ? k : k + 290;
            int n = n0 + nn;
            Ds[kk*DPAD + nn] = (n < NN) ? SD[n*350 + lsel] : 0.f;
        }
        __syncthreads();
#pragma unroll
        for (int kk = 0; kk < KA_; kk++) {
            float4 f  = *(const float4*)&Fs[kk*BM_ + ty*4];
            float4 d0 = *(const float4*)&Ds[kk*DPAD + tx*8];
            float4 d1 = *(const float4*)&Ds[kk*DPAD + tx*8 + 4];
            float fv[4] = {f.x, f.y, f.z, f.w};
            float dv[8] = {d0.x, d0.y, d0.z, d0.w, d1.x, d1.y, d1.z, d1.w};
#pragma unroll
            for (int i = 0; i < 4; i++)
#pragma unroll
                for (int jj = 0; jj < 8; jj++) acc[i][jj] += fv[i]*dv[jj];
        }
        __syncthreads();
    }

    // ---- phase B: posedirs, k=60..545 in 27 18-chunks ----
    for (int cchunk = 0; cchunk < 27; cchunk++) {
        int k0 = KSH + cchunk*KB_;
        for (int e = tid; e < KB_*BM_; e += 256) {
            int kk = e / BM_, bb = e % BM_;
            Fs[kk*BM_ + bb] = g_Ft[(k0+kk)*BS + b0 + bb];
        }
        for (int e = tid; e < KB_*BN_; e += 256) {
            int nn = e % BN_, kk = e / BN_;
            int n = n0 + nn;
            Ds[kk*DPAD + nn] = (n < NN) ? PD[(k0-KSH+kk)*NN + n] : 0.f;
        }
        __syncthreads();
#pragma unroll
        for (int kk = 0; kk < KB_; kk++) {
            float4 f  = *(const float4*)&Fs[kk*BM_ + ty*4];
            float4 d0 = *(const float4*)&Ds[kk*DPAD + tx*8];
            float4 d1 = *(const float4*)&Ds[kk*DPAD + tx*8 + 4];
            float fv[4] = {f.x, f.y, f.z, f.w};
            float dv[8] = {d0.x, d0.y, d0.z, d0.w, d1.x, d1.y, d1.z, d1.w};
#pragma unroll
            for (int i = 0; i < 4; i++)
#pragma unroll
                for (int jj = 0; jj < 8; jj++) acc[i][jj] += fv[i]*dv[jj];
        }
        __syncthreads();
    }

    // ---- epilogue ----
#pragma unroll
    for (int i = 0; i < 4; i++) {
        int b = b0 + ty*4 + i;
#pragma unroll
        for (int jj = 0; jj < 8; jj++) {
            int n = n0 + tx*8 + jj;
            if (n < NN) g_vposed[b*NN + n] = acc[i][jj] + vt[n];
        }
    }
}

// ============================================================================
// K7: LBS skinning. Block = 192 verts x 8 batches (w staged once, reused 8x).
//     Thread: 3 verts, 12-entry T accumulator each; then transform v_posed.
// ============================================================================
#define LVT 192
#define BGRP 8
__global__ __launch_bounds__(64) void k_lbs(const float* __restrict__ W,
                                            float* __restrict__ verts) {
    int vbase = blockIdx.x * LVT;
    int b0 = blockIdx.y * BGRP;
    int t = threadIdx.x;
    __shared__ float As[NJ*12];
    __shared__ float ws[NJ*193];
    // stage weights, transposed: ws[j][v_local]  (coalesced global read)
    for (int e = t; e < NJ*LVT; e += 64) {
        int vl = e / 55, j = e % 55;
        int v = vbase + vl;
        ws[j*193 + vl] = (v < NV) ? W[v*55 + j] : 0.f;
    }
    for (int bi = 0; bi < BGRP; bi++) {
        int b = b0 + bi;
        __syncthreads();
        for (int e = t; e < 660; e += 64) As[e] = g_Arel[b*660 + e];
        __syncthreads();
        float acc[3][12];
#pragma unroll
        for (int i = 0; i < 3; i++)
#pragma unroll
            for (int k = 0; k < 12; k++) acc[i][k] = 0.f;
#pragma unroll 5
        for (int j = 0; j < NJ; j++) {
            float4 a0 = *(const float4*)&As[j*12];
            float4 a1 = *(const float4*)&As[j*12+4];
            float4 a2 = *(const float4*)&As[j*12+8];
#pragma unroll
            for (int i = 0; i < 3; i++) {
                float wv = ws[j*193 + t*3 + i];
                acc[i][0] += wv*a0.x; acc[i][1] += wv*a0.y; acc[i][2]  += wv*a0.z; acc[i][3]  += wv*a0.w;
                acc[i][4] += wv*a1.x; acc[i][5] += wv*a1.y; acc[i][6]  += wv*a1.z; acc[i][7]  += wv*a1.w;
                acc[i][8] += wv*a2.x; acc[i][9] += wv*a2.y; acc[i][10] += wv*a2.z; acc[i][11] += wv*a2.w;
            }
        }
#pragma unroll
        for (int i = 0; i < 3; i++) {
            int v = vbase + t*3 + i;
            if (v < NV) {
                const float* p = &g_vposed[b*NN + v*3];
                float p0 = p[0], p1 = p[1], p2 = p[2];
                float o0 = acc[i][0]*p0 + acc[i][1]*p1 + acc[i][2] *p2 + acc[i][3];
                float o1 = acc[i][4]*p0 + acc[i][5]*p1 + acc[i][6] *p2 + acc[i][7];
                float o2 = acc[i][8]*p0 + acc[i][9]*p1 + acc[i][10]*p2 + acc[i][11];
                float* o = verts + b*NN + v*3;
                o[0] = o0; o[1] = o1; o[2] = o2;
            }
        }
    }
}

// ============================================================================
extern "C" void kernel_launch(void* const* d_in, const int* in_sizes, int n_in,
                              void* d_out, int out_size) {
    const float* pose  = (const float*)d_in[0];   // (256,53,3)
    const float* shape = (const float*)d_in[1];   // (256,10)
    const float* expr  = (const float*)d_in[2];   // (256,50)
    const float* go    = (const float*)d_in[3];   // (1,3)
    const float* vt    = (const float*)d_in[4];   // (10475,3)
    const float* SD    = (const float*)d_in[5];   // (10475,3,350)
    const float* PD    = (const float*)d_in[6];   // (486,31425)
    const float* Jr    = (const float*)d_in[7];   // (55,10475)
    const float* W     = (const float*)d_in[8];   // (10475,55)
    float* out_verts  = (float*)d_out;                   // (256,10475,3)
    float* out_joints = (float*)d_out + (size_t)BS*NN;   // (256,55,3)

    k_pose  <<<BS, 64>>>(pose, shape, expr, go);
    k_jsdp  <<<dim3(NJ, 8), 192>>>(Jr, SD, vt);
    k_jsdf  <<<NJ, 192>>>();
    k_joints<<<BS, 192>>>();
    k_chain <<<BS, 32>>>(out_joints);
    k_blend <<<dim3((NN + BN_ - 1)/BN_, BS/BM_), 256>>>(SD, PD, vt);
    k_lbs   <<<dim3((NV + LVT - 1)/LVT, BS/BGRP), 64>>>(W, out_verts);
}

// round 8
// speedup vs baseline: 1.0377x; 1.0377x over previous
#include <cuda_runtime.h>
#include <cstdint>
#include <math.h>

#define BS   256
#define NJ   55
#define NV   10475
#define NN   (NV*3)      // 31425
#define KSH  60
#define KTOT 546
#define KPAD 576
#define PITCH 133

__constant__ int c_parents[NJ] = {-1,0,0,0,1,2,3,4,5,6,7,8,9,9,9,12,13,14,16,17,18,19,
                                  15,15,15,20,25,26,20,28,29,20,31,32,20,34,35,20,37,38,
                                  21,40,41,21,43,44,21,46,47,21,49,50,21,52,53};

// ---- scratch ----
__device__ float g_F[BS*KPAD];             // feature matrix row-major [b][k], zero-padded
__device__ float g_rot[BS*NJ*9];
__device__ float g_JSDp[8*NJ*184];
__device__ float g_JSD[NJ*180];
__device__ float g_Jvt[NJ*3];
__device__ float g_joints[BS*NJ*3];
__device__ float g_Arel[BS*NJ*12];
__device__ float g_vposed[BS*NN];          // 32.2 MB

// ============================================================================
// tf32 warp MMA helpers (standard PTX, compiles for plain sm_103)
// ============================================================================
__device__ __forceinline__ uint32_t tf32u(float v){
    uint32_t r; asm("cvt.rn.tf32.f32 %0,%1;":"=r"(r):"f"(v)); return r;
}
__device__ __forceinline__ void mma8(float& d0, float& d1, float& d2, float& d3,
                                     uint32_t a0, uint32_t a1, uint32_t a2, uint32_t a3,
                                     uint32_t b0, uint32_t b1){
    asm volatile("mma.sync.aligned.m16n8k8.row.col.f32.tf32.tf32.f32 "
                 "{%0,%1,%2,%3},{%4,%5,%6,%7},{%8,%9},{%0,%1,%2,%3};"
                 : "+f"(d0), "+f"(d1), "+f"(d2), "+f"(d3)
                 : "r"(a0), "r"(a1), "r"(a2), "r"(a3), "r"(b0), "r"(b1));
}

// ============================================================================
// K1: Rodrigues + feature matrix build
// ============================================================================
__global__ void k_pose(const float* __restrict__ pose, const float* __restrict__ shape,
                       const float* __restrict__ expr, const float* __restrict__ go) {
    int b = blockIdx.x, t = threadIdx.x;
    for (int i = t; i < KPAD-KTOT; i += 64) g_F[b*KPAD + KTOT + i] = 0.f;
    if (t < NJ) {
        int j = t;
        float rx, ry, rz;
        if (j == 0)            { rx = go[0]; ry = go[1]; rz = go[2]; }
        else if (j==23||j==24) { rx = 0.f; ry = 0.f; rz = 0.f; }
        else {
            int src = (j <= 21) ? j : (j == 22 ? 52 : j - 3);
            const float* p = pose + (b*53 + src)*3;
            rx = p[0]; ry = p[1]; rz = p[2];
        }
        float ax = rx + 1e-8f, ay = ry + 1e-8f, az = rz + 1e-8f;
        float angle = sqrtf(ax*ax + ay*ay + az*az);
        float inv = 1.f/angle;
        float x = rx*inv, y = ry*inv, z = rz*inv;
        float s = sinf(angle), c = cosf(angle), u = 1.f - c;
        float R[9];
        R[0] = 1.f - u*(y*y+z*z); R[1] = -s*z + u*x*y;      R[2] =  s*y + u*x*z;
        R[3] =  s*z + u*x*y;      R[4] = 1.f - u*(x*x+z*z); R[5] = -s*x + u*y*z;
        R[6] = -s*y + u*x*z;      R[7] =  s*x + u*y*z;      R[8] = 1.f - u*(x*x+y*y);
        float* rm = g_rot + (b*NJ + j)*9;
#pragma unroll
        for (int k = 0; k < 9; k++) rm[k] = R[k];
        if (j >= 1) {
            int kb = KSH + (j-1)*9;
#pragma unroll
            for (int k = 0; k < 9; k++)
                g_F[b*KPAD + kb + k] = R[k] - ((k==0||k==4||k==8) ? 1.f : 0.f);
        }
    }
    for (int i = t; i < KSH; i += 64)
        g_F[b*KPAD + i] = (i < 10) ? shape[b*10 + i] : expr[b*50 + (i-10)];
}

// ============================================================================
// K2: JSD partials, 5 joints per block
// ============================================================================
#define VCH 1310
__global__ void k_jsdp(const float* __restrict__ Jr, const float* __restrict__ SD,
                       const float* __restrict__ vt) {
    int jg = blockIdx.x, ch = blockIdx.y, t = threadIdx.x;
    int v0 = ch*VCH;
    int cnt = min(VCH, NV - v0);
    __shared__ float jr_s[5][VCH+2];
    for (int u = 0; u < 5; u++)
        for (int i = t; i < cnt; i += 192) jr_s[u][i] = Jr[(jg*5+u)*NV + v0 + i];
    __syncthreads();
    float acc[5] = {0.f,0.f,0.f,0.f,0.f};
    if (t < 180) {
        int c = t/60, lx = t%60;
        int ls = (lx < 10) ? lx : lx + 290;
        const float* base = SD + c*350 + ls + (size_t)v0*1050;
#pragma unroll 2
        for (int i = 0; i < cnt; i++) {
            float sv = base[(size_t)i*1050];
#pragma unroll
            for (int u = 0; u < 5; u++) acc[u] += jr_s[u][i]*sv;
        }
    } else if (t < 183) {
        int c = t - 180;
#pragma unroll 2
        for (int i = 0; i < cnt; i++) {
            float sv = vt[(v0+i)*3 + c];
#pragma unroll
            for (int u = 0; u < 5; u++) acc[u] += jr_s[u][i]*sv;
        }
    }
    if (t < 183)
        for (int u = 0; u < 5; u++)
            g_JSDp[(ch*NJ + jg*5 + u)*184 + t] = acc[u];
}

__global__ void k_jsdf() {
    int j = blockIdx.x, t = threadIdx.x;
    if (t >= 183) return;
    float s = 0.f;
#pragma unroll
    for (int ch = 0; ch < 8; ch++) s += g_JSDp[(ch*NJ + j)*184 + t];
    if (t < 180) g_JSD[j*180 + t] = s;
    else         g_Jvt[j*3 + (t-180)] = s;
}

// ============================================================================
// K4: joints
// ============================================================================
__global__ void k_joints() {
    int b = blockIdx.x, t = threadIdx.x;
    __shared__ float fb[KSH];
    for (int i = t; i < KSH; i += 192) fb[i] = g_F[b*KPAD + i];
    __syncthreads();
    if (t < 165) {
        int j = t/3, c = t%3;
        float acc = g_Jvt[j*3 + c];
        const float* jsd = g_JSD + j*180 + c*60;
#pragma unroll
        for (int l = 0; l < KSH; l++) acc += fb[l]*jsd[l];
        g_joints[b*165 + t] = acc;
    }
}

// ============================================================================
// K5: kinematic chain
// ============================================================================
__global__ void k_chain(float* __restrict__ out_joints) {
    int b = blockIdx.x, t = threadIdx.x;
    __shared__ float A[NJ][12];
    __shared__ float jt[NJ][3];
    for (int i = t; i < 165; i += 32) jt[i/3][i%3] = g_joints[b*165 + i];
    __syncwarp();
    if (t < 12) {
        int m = t/4, n = t%4;
        A[0][t] = (n < 3) ? g_rot[(b*NJ)*9 + m*3 + n] : jt[0][m];
    }
    __syncwarp();
    for (int j = 1; j < NJ; j++) {
        if (t < 12) {
            int m = t/4, n = t%4;
            int p = c_parents[j];
            const float* rm = g_rot + (b*NJ + j)*9;
            float acc = (n == 3) ? A[p][m*4+3] : 0.f;
#pragma unroll
            for (int k = 0; k < 3; k++) {
                float tv = (n < 3) ? rm[k*3+n] : (jt[j][k] - jt[p][k]);
                acc += A[p][m*4+k]*tv;
            }
            A[j][t] = acc;
        }
        __syncwarp();
    }
    for (int e = t; e < 660; e += 32) {
        int j = e/12, r = e%12, m = r/4, n = r%4;
        float val = A[j][r];
        if (n == 3) {
            out_joints[b*165 + j*3 + m] = val;
            val -= A[j][m*4+0]*jt[j][0] + A[j][m*4+1]*jt[j][1] + A[j][m*4+2]*jt[j][2];
        }
        g_Arel[b*660 + e] = val;
    }
}

// ============================================================================
// K6: blend GEMM via mma.sync tf32. CTA 128(b) x 128(n), K=576 in 18 chunks.
// 8 warps = 2(M) x 4(N); warp tile 64x32 = 16 m16n8k8 per k-step.
// ============================================================================
__global__ __launch_bounds__(256) void k_blend_mma(const float* __restrict__ SD,
                                                   const float* __restrict__ PD,
                                                   const float* __restrict__ vt) {
    __shared__ uint32_t As[32*PITCH];   // [k][m] tf32
    __shared__ uint32_t Bsm[32*PITCH];  // [k][n] tf32
    int tid = threadIdx.x, lane = tid & 31, w = tid >> 5;
    int wm = w >> 2, wn = w & 3;
    int gid = lane >> 2, tig = lane & 3;
    int n0 = blockIdx.x*128, b0 = blockIdx.y*128;

    float acc[4][4][4];
#pragma unroll
    for (int mi = 0; mi < 4; mi++)
#pragma unroll
        for (int ni = 0; ni < 4; ni++)
#pragma unroll
            for (int q = 0; q < 4; q++) acc[mi][ni][q] = 0.f;

    for (int c = 0; c < 18; c++) {
        int k0 = c*32;
        // A fill: float4 LDG from g_F (coalesced), scalar STS (conflict-free)
#pragma unroll
        for (int ii = 0; ii < 4; ii++) {
            int idx = tid + ii*256;          // 0..1023 float4 slots
            int m = idx >> 3, kq = idx & 7;  // 128 m x 8 quads
            float4 v = *(const float4*)&g_F[(b0+m)*KPAD + k0 + kq*4];
            As[(kq*4+0)*PITCH + m] = tf32u(v.x);
            As[(kq*4+1)*PITCH + m] = tf32u(v.y);
            As[(kq*4+2)*PITCH + m] = tf32u(v.z);
            As[(kq*4+3)*PITCH + m] = tf32u(v.w);
        }
        // B fill: scalar LDG (n contiguous -> coalesced), STS conflict-free
#pragma unroll
        for (int ii = 0; ii < 16; ii++) {
            int idx = tid + ii*256;          // 0..4095
            int n = idx & 127, k = idx >> 7;
            int kg = k0 + k, ng = n0 + n;
            float v = 0.f;
            if (ng < NN) {
                if (kg < KSH)       { int ls = (kg < 10) ? kg : kg + 290; v = SD[(size_t)ng*350 + ls]; }
                else if (kg < KTOT) { v = PD[(size_t)(kg-KSH)*NN + ng]; }
            }
            Bsm[k*PITCH + n] = tf32u(v);
        }
        __syncthreads();
#pragma unroll
        for (int s = 0; s < 4; s++) {
            int ks = s*8;
            uint32_t af[4][4], bf[4][2];
#pragma unroll
            for (int mi = 0; mi < 4; mi++) {
                int row = wm*64 + mi*16 + gid;
                af[mi][0] = As[(ks+tig  )*PITCH + row];
                af[mi][1] = As[(ks+tig  )*PITCH + row + 8];
                af[mi][2] = As[(ks+tig+4)*PITCH + row];
                af[mi][3] = As[(ks+tig+4)*PITCH + row + 8];
            }
#pragma unroll
            for (int ni = 0; ni < 4; ni++) {
                int col = wn*32 + ni*8 + gid;
                bf[ni][0] = Bsm[(ks+tig  )*PITCH + col];
                bf[ni][1] = Bsm[(ks+tig+4)*PITCH + col];
            }
#pragma unroll
            for (int mi = 0; mi < 4; mi++)
#pragma unroll
                for (int ni = 0; ni < 4; ni++)
                    mma8(acc[mi][ni][0], acc[mi][ni][1], acc[mi][ni][2], acc[mi][ni][3],
                         af[mi][0], af[mi][1], af[mi][2], af[mi][3],
                         bf[ni][0], bf[ni][1]);
        }
        __syncthreads();
    }
    // epilogue: add v_template, write v_posed
#pragma unroll
    for (int mi = 0; mi < 4; mi++) {
        int r0 = b0 + wm*64 + mi*16 + gid;
#pragma unroll
        for (int ni = 0; ni < 4; ni++) {
            int cc = wn*32 + ni*8 + 2*tig;
            int n = n0 + cc;
            if (n+1 < NN) {
                g_vposed[(size_t)r0*NN + n]       = acc[mi][ni][0] + vt[n];
                g_vposed[(size_t)r0*NN + n+1]     = acc[mi][ni][1] + vt[n+1];
                g_vposed[(size_t)(r0+8)*NN + n]   = acc[mi][ni][2] + vt[n];
                g_vposed[(size_t)(r0+8)*NN + n+1] = acc[mi][ni][3] + vt[n+1];
            } else if (n < NN) {
                g_vposed[(size_t)r0*NN + n]       = acc[mi][ni][0] + vt[n];
                g_vposed[(size_t)(r0+8)*NN + n]   = acc[mi][ni][2] + vt[n];
            }
        }
    }
}

// ============================================================================
// K7: LBS via mma.sync tf32. CTA: 128 verts x 128 (8 batches x 16 cols), K=64.
// D staged through smem (reusing A/B region) for the transform epilogue.
// ============================================================================
__global__ __launch_bounds__(256) void k_lbs_mma(const float* __restrict__ W,
                                                 float* __restrict__ verts) {
    extern __shared__ uint32_t sm[];
    uint32_t* As  = sm;               // [64][PITCH]
    uint32_t* Bsm = sm + 64*PITCH;    // [64][PITCH]
    float*    Ds  = (float*)sm;       // [128][132] (reused after MMA)
    int tid = threadIdx.x, lane = tid & 31, w = tid >> 5;
    int wm = w >> 2, wn = w & 3;
    int gid = lane >> 2, tig = lane & 3;
    int vbase = blockIdx.x*128, b0 = blockIdx.y*8;

    // A fill: W tile [v=128][j=64]; STS As[j][v] conflict-free (5j+v perm)
#pragma unroll
    for (int ii = 0; ii < 32; ii++) {
        int idx = tid + ii*256;
        int j = idx & 63, vl = idx >> 6;
        int v = vbase + vl;
        float val = (j < NJ && v < NV) ? W[(size_t)v*NJ + j] : 0.f;
        As[j*PITCH + vl] = tf32u(val);
    }
    // B fill: Arel tile [j=64][n=128], n=(bi,q)
#pragma unroll
    for (int ii = 0; ii < 32; ii++) {
        int idx = tid + ii*256;
        int n = idx & 127, j = idx >> 7;
        int bi = n >> 4, q = n & 15;
        float val = (q < 12 && j < NJ) ? g_Arel[(b0+bi)*660 + j*12 + q] : 0.f;
        Bsm[j*PITCH + n] = tf32u(val);
    }
    __syncthreads();

    float acc[4][4][4];
#pragma unroll
    for (int mi = 0; mi < 4; mi++)
#pragma unroll
        for (int ni = 0; ni < 4; ni++)
#pragma unroll
            for (int q = 0; q < 4; q++) acc[mi][ni][q] = 0.f;

#pragma unroll
    for (int s = 0; s < 8; s++) {
        int ks = s*8;
        uint32_t af[4][4], bf[4][2];
#pragma unroll
        for (int mi = 0; mi < 4; mi++) {
            int row = wm*64 + mi*16 + gid;
            af[mi][0] = As[(ks+tig  )*PITCH + row];
            af[mi][1] = As[(ks+tig  )*PITCH + row + 8];
            af[mi][2] = As[(ks+tig+4)*PITCH + row];
            af[mi][3] = As[(ks+tig+4)*PITCH + row + 8];
        }
#pragma unroll
        for (int ni = 0; ni < 4; ni++) {
            int col = wn*32 + ni*8 + gid;
            bf[ni][0] = Bsm[(ks+tig  )*PITCH + col];
            bf[ni][1] = Bsm[(ks+tig+4)*PITCH + col];
        }
#pragma unroll
        for (int mi = 0; mi < 4; mi++)
#pragma unroll
            for (int ni = 0; ni < 4; ni++)
                mma8(acc[mi][ni][0], acc[mi][ni][1], acc[mi][ni][2], acc[mi][ni][3],
                     af[mi][0], af[mi][1], af[mi][2], af[mi][3],
                     bf[ni][0], bf[ni][1]);
    }
    __syncthreads();   // all warps done reading As/Bsm

    // write D to smem [row][132]
#pragma unroll
    for (int mi = 0; mi < 4; mi++) {
        int r = wm*64 + mi*16 + gid;
#pragma unroll
        for (int ni = 0; ni < 4; ni++) {
            int cc = wn*32 + ni*8 + 2*tig;
            *(float2*)&Ds[r*132 + cc]     = make_float2(acc[mi][ni][0], acc[mi][ni][1]);
            *(float2*)&Ds[(r+8)*132 + cc] = make_float2(acc[mi][ni][2], acc[mi][ni][3]);
        }
    }
    __syncthreads();

    // transform epilogue: 128 rows x 8 batches = 1024 tasks, 4 per thread
#pragma unroll
    for (int ii = 0; ii < 4; ii++) {
        int id = tid + ii*256;
        int row = id & 127, bi = id >> 7;
        int v = vbase + row;
        if (v < NV) {
            int b = b0 + bi;
            const float* T = Ds + row*132 + bi*16;
            const float* p = g_vposed + (size_t)b*NN + v*3;
            float p0 = p[0], p1 = p[1], p2 = p[2];
            float* o = verts + (size_t)b*NN + v*3;
#pragma unroll
            for (int m = 0; m < 3; m++)
                o[m] = T[4*m+0]*p0 + T[4*m+1]*p1 + T[4*m+2]*p2 + T[4*m+3];
        }
    }
}

// ============================================================================
extern "C" void kernel_launch(void* const* d_in, const int* in_sizes, int n_in,
                              void* d_out, int out_size) {
    const float* pose  = (const float*)d_in[0];
    const float* shape = (const float*)d_in[1];
    const float* expr  = (const float*)d_in[2];
    const float* go    = (const float*)d_in[3];
    const float* vt    = (const float*)d_in[4];
    const float* SD    = (const float*)d_in[5];
    const float* PD    = (const float*)d_in[6];
    const float* Jr    = (const float*)d_in[7];
    const float* W     = (const float*)d_in[8];
    float* out_verts  = (float*)d_out;
    float* out_joints = (float*)d_out + (size_t)BS*NN;

    int lbs_smem = 2*64*PITCH*4;   // 68096 B (also covers 128*132*4 = 67584)
    cudaFuncSetAttribute(k_lbs_mma, cudaFuncAttributeMaxDynamicSharedMemorySize, lbs_smem);

    k_pose     <<<BS, 64>>>(pose, shape, expr, go);
    k_jsdp     <<<dim3(11, 8), 192>>>(Jr, SD, vt);
    k_jsdf     <<<NJ, 192>>>();
    k_joints   <<<BS, 192>>>();
    k_chain    <<<BS, 32>>>(out_joints);
    k_blend_mma<<<dim3(246, 2), 256>>>(SD, PD, vt);
    k_lbs_mma  <<<dim3(82, 32), 256, lbs_smem>>>(W, out_verts);
}